// round 15
// baseline (speedup 1.0000x reference)
#include <cuda_runtime.h>
#include <cuda_fp16.h>
#include <cstdint>
#include <math.h>

#define BSZ 2
#define SEQ 2048
#define EMB 2048
#define NH  16
#define HD  128
#define E3  (3*EMB)
#define ROWS (BSZ*SEQ)
#define SCALE 0.08838834764831845f

// ---------------- static device scratch (no allocations) ------------------
__device__ __half g_hid_hi[(size_t)ROWS * EMB];
__device__ __half g_qkv_hi[(size_t)ROWS * E3];
__device__ __half g_attn_hi[(size_t)ROWS * EMB];
__device__ __half g_wfT_hi[(size_t)E3 * EMB];
__device__ __half g_wpT_hi[(size_t)EMB * EMB];
__device__ __half g_vt_hi[(size_t)BSZ * NH * HD * SEQ];
__device__ __half g_p_hi[(size_t)BSZ * NH * SEQ * SEQ];
__device__ float2 g_part[(size_t)BSZ * NH * SEQ * 16];   // per (row, m-tile) stats
__device__ float2 g_rowstat[(size_t)BSZ * NH * SEQ];     // per row (max, 1/sum)

// ---------------- tile geometry (all GEMMs single-pass, KC=64) -------------
#define T64STR 72
#define T64B   (128 * T64STR * 2)      // 18432 B
#define SNG_STAGE (2 * T64B)           // A, B = 36864 B
#define SM_SNG (3 * SNG_STAGE)         // 110592 B -> 2 CTAs/SM (221 KB)

__device__ __forceinline__ uint32_t smem_u32(const void* p) {
    uint32_t a;
    asm("{ .reg .u64 t; cvta.to.shared.u64 t, %1; cvt.u32.u64 %0, t; }"
        : "=r"(a) : "l"(p));
    return a;
}
__device__ __forceinline__ void cpa16(uint32_t d, const void* s) {
    asm volatile("cp.async.cg.shared.global [%0], [%1], 16;" :: "r"(d), "l"(s) : "memory");
}
#define CP_COMMIT() asm volatile("cp.async.commit_group;" ::: "memory")
#define CP_WAIT1()  asm volatile("cp.async.wait_group 1;" ::: "memory")

#define LDMX4(r, a)                                                          \
    asm volatile("ldmatrix.sync.aligned.m8n8.x4.shared.b16 {%0,%1,%2,%3}, [%4];" \
                 : "=r"((r)[0]), "=r"((r)[1]), "=r"((r)[2]), "=r"((r)[3]) : "r"(a))

#define MMA16816(d, a, b0v, b1v)                                             \
    asm volatile("mma.sync.aligned.m16n8k16.row.col.f32.f16.f16.f32 "        \
                 "{%0,%1,%2,%3}, {%4,%5,%6,%7}, {%8,%9}, {%0,%1,%2,%3};"     \
                 : "+f"((d)[0]), "+f"((d)[1]), "+f"((d)[2]), "+f"((d)[3])    \
                 : "r"((a)[0]), "r"((a)[1]), "r"((a)[2]), "r"((a)[3]),       \
                   "r"(b0v), "r"(b1v))

__device__ __forceinline__ uint32_t round_pair_h(float x, float y) {
    __half2 H = __floats2half2_rn(x, y);
    return *reinterpret_cast<uint32_t*>(&H);
}
__device__ __forceinline__ void stcs_f2(float* p, float2 v) {
    asm volatile("st.global.cs.v2.f32 [%0], {%1,%2};" :: "l"(p), "f"(v.x), "f"(v.y) : "memory");
}
__device__ __forceinline__ void stcs_f4(float* p, float4 v) {
    asm volatile("st.global.cs.v4.f32 [%0], {%1,%2,%3,%4};"
                 :: "l"(p), "f"(v.x), "f"(v.y), "f"(v.z), "f"(v.w) : "memory");
}
__device__ __forceinline__ void stcs_u2(void* p, uint2 v) {
    asm volatile("st.global.cs.v2.u32 [%0], {%1,%2};" :: "l"(p), "r"(v.x), "r"(v.y) : "memory");
}

// ======================= single-A GEMM core (KC=64, 3-stage) ===============
__device__ __forceinline__ void issue64(const __half* __restrict__ ah, int lda,
                                        const __half* __restrict__ bh, int ldb,
                                        uint32_t stage, int tid) {
#pragma unroll
    for (int i = 0; i < 4; i++) {
        int f = tid + i * 256;
        int r = f >> 3, kg = f & 7;
        uint32_t off = (uint32_t)(r * 144 + kg * 16);
        cpa16(stage + off, ah + (size_t)r * lda + kg * 8);
        cpa16(stage + T64B + off, bh + (size_t)r * ldb + kg * 8);
    }
}

__device__ __forceinline__ void mma64(uint32_t st, int warp_m, int warp_n,
                                      int lane, float acc[2][8][4]) {
    const int arow = (lane & 7) + ((lane >> 3) & 1) * 8;
    const int acol = (lane >> 4) * 8;
    const int brow = (lane & 7) + (lane >> 4) * 8;
    const int bcol = ((lane >> 3) & 1) * 8;
#pragma unroll
    for (int k16 = 0; k16 < 4; k16++) {
        const int k0 = k16 * 16;
        uint32_t ah[2][4];
#pragma unroll
        for (int mt = 0; mt < 2; mt++) {
            uint32_t a = st +
                (uint32_t)((warp_m * 32 + mt * 16 + arow) * T64STR + k0 + acol) * 2;
            LDMX4(ah[mt], a);
        }
#pragma unroll
        for (int np = 0; np < 4; np++) {
            uint32_t b = st + T64B +
                (uint32_t)((warp_n * 64 + np * 16 + brow) * T64STR + k0 + bcol) * 2;
            uint32_t bh[4];
            LDMX4(bh, b);
#pragma unroll
            for (int mt = 0; mt < 2; mt++) {
                MMA16816(acc[mt][2 * np],     ah[mt], bh[0], bh[1]);
                MMA16816(acc[mt][2 * np + 1], ah[mt], bh[2], bh[3]);
            }
        }
    }
}

__device__ __forceinline__ void pipe_single(
    const __half* ah, int lda, const __half* bh, int ldb, int nch, uint32_t sb,
    int tid, int warp_m, int warp_n, int lane, float acc[2][8][4])
{
#pragma unroll
    for (int s = 0; s < 2; s++) {
        if (s < nch) issue64(ah + s * 64, lda, bh + s * 64, ldb,
                             sb + s * SNG_STAGE, tid);
        CP_COMMIT();
    }
    for (int c = 0; c < nch; c++) {
        CP_WAIT1();
        __syncthreads();
        mma64(sb + (c % 3) * SNG_STAGE, warp_m, warp_n, lane, acc);
        if (c + 2 < nch)
            issue64(ah + (c + 2) * 64, lda, bh + (c + 2) * 64, ldb,
                    sb + ((c + 2) % 3) * SNG_STAGE, tid);
        CP_COMMIT();
    }
}

#define GEMM_DECL()                                                          \
    extern __shared__ char smc[];                                            \
    uint32_t sb = smem_u32(smc);                                             \
    const int tid = threadIdx.x;                                             \
    const int wid = tid >> 5, lane = tid & 31;                               \
    const int warp_m = wid & 3, warp_n = wid >> 2;                           \
    float acc[2][8][4];                                                      \
    _Pragma("unroll") for (int i = 0; i < 2; i++)                            \
    _Pragma("unroll") for (int j = 0; j < 8; j++)                            \
    _Pragma("unroll") for (int q = 0; q < 4; q++) acc[i][j][q] = 0.0f;

// triangular tile index q -> (nq, mq)
__device__ __forceinline__ void tri_index(int q, int& nq, int& mq) {
    nq = (int)((sqrtf(8.0f * (float)q + 1.0f) - 1.0f) * 0.5f);
    while ((nq + 1) * (nq + 2) / 2 <= q) nq++;
    while (nq * (nq + 1) / 2 > q) nq--;
    mq = q - nq * (nq + 1) / 2;
}

// ===========================================================================
__global__ __launch_bounds__(256, 2) void gemm_qkv() {
    GEMM_DECL();
    const int m0 = blockIdx.y * 128, n0 = blockIdx.x * 128;
    pipe_single(g_hid_hi + (size_t)m0 * EMB, EMB,
                g_wfT_hi + (size_t)n0 * EMB, EMB,
                EMB / 64, sb, tid, warp_m, warp_n, lane, acc);
    const int g = lane >> 2, t = lane & 3;
#pragma unroll
    for (int mt = 0; mt < 2; mt++)
#pragma unroll
        for (int nt = 0; nt < 8; nt++) {
            int r = m0 + warp_m * 32 + mt * 16 + g;
            int c = n0 + warp_n * 64 + nt * 8 + t * 2;
            size_t o0 = (size_t)r * E3 + c, o1 = (size_t)(r + 8) * E3 + c;
            *reinterpret_cast<uint32_t*>(g_qkv_hi + o0) =
                round_pair_h(acc[mt][nt][0], acc[mt][nt][1]);
            *reinterpret_cast<uint32_t*>(g_qkv_hi + o1) =
                round_pair_h(acc[mt][nt][2], acc[mt][nt][3]);
        }
}

// ===========================================================================
// scores pass1: QK^T on tri tiles; reduce tile -> per-row (max, sumexp).
__global__ __launch_bounds__(256, 2) void scores_p1() {
    const int bh2 = blockIdx.z, b = bh2 >> 4, h = bh2 & 15;
    int nq, mq; tri_index(blockIdx.x, nq, mq);
    const int n0 = nq * 128, m0 = mq * 128;
    GEMM_DECL();
    const float NEG_INF = __int_as_float(0xff800000);
    const size_t qoff = (size_t)b * SEQ * E3 + (size_t)n0 * E3 + h * HD;
    const size_t koff = (size_t)b * SEQ * E3 + (size_t)m0 * E3 + EMB + h * HD;
    pipe_single(g_qkv_hi + qoff, E3, g_qkv_hi + koff, E3,
                HD / 64, sb, tid, warp_m, warp_n, lane, acc);
    const int g = lane >> 2, t = lane & 3;

    // mask + scale in place
#pragma unroll
    for (int mt = 0; mt < 2; mt++)
#pragma unroll
        for (int nt = 0; nt < 8; nt++) {
            int r = n0 + warp_m * 32 + mt * 16 + g;
            int c = m0 + warp_n * 64 + nt * 8 + t * 2;
            acc[mt][nt][0] = (c     <= r)     ? acc[mt][nt][0] * SCALE : NEG_INF;
            acc[mt][nt][1] = (c + 1 <= r)     ? acc[mt][nt][1] * SCALE : NEG_INF;
            acc[mt][nt][2] = (c     <= r + 8) ? acc[mt][nt][2] * SCALE : NEG_INF;
            acc[mt][nt][3] = (c + 1 <= r + 8) ? acc[mt][nt][3] * SCALE : NEG_INF;
        }

    __syncthreads();                   // pipeline done; reuse smem
    float* red = reinterpret_cast<float*>(smc);   // [2][128]

    float rmax[2][2];
#pragma unroll
    for (int mt = 0; mt < 2; mt++)
#pragma unroll
        for (int hf = 0; hf < 2; hf++) {
            float lm = NEG_INF;
#pragma unroll
            for (int nt = 0; nt < 8; nt++)
                lm = fmaxf(lm, fmaxf(acc[mt][nt][hf * 2], acc[mt][nt][hf * 2 + 1]));
            lm = fmaxf(lm, __shfl_xor_sync(0xFFFFFFFFu, lm, 1));
            lm = fmaxf(lm, __shfl_xor_sync(0xFFFFFFFFu, lm, 2));
            int rl = warp_m * 32 + mt * 16 + hf * 8 + g;
            if (t == 0) red[warp_n * 128 + rl] = lm;
        }
    __syncthreads();
#pragma unroll
    for (int mt = 0; mt < 2; mt++)
#pragma unroll
        for (int hf = 0; hf < 2; hf++) {
            int rl = warp_m * 32 + mt * 16 + hf * 8 + g;
            rmax[mt][hf] = fmaxf(red[rl], red[128 + rl]);
        }
    __syncthreads();
#pragma unroll
    for (int mt = 0; mt < 2; mt++)
#pragma unroll
        for (int hf = 0; hf < 2; hf++) {
            float ls = 0.0f;
#pragma unroll
            for (int nt = 0; nt < 8; nt++)
                ls += __expf(acc[mt][nt][hf * 2]     - rmax[mt][hf]) +
                      __expf(acc[mt][nt][hf * 2 + 1] - rmax[mt][hf]);
            ls += __shfl_xor_sync(0xFFFFFFFFu, ls, 1);
            ls += __shfl_xor_sync(0xFFFFFFFFu, ls, 2);
            int rl = warp_m * 32 + mt * 16 + hf * 8 + g;
            if (t == 0) red[warp_n * 128 + rl] = ls;
        }
    __syncthreads();
    if (warp_n == 0 && t == 0) {
#pragma unroll
        for (int mt = 0; mt < 2; mt++)
#pragma unroll
            for (int hf = 0; hf < 2; hf++) {
                int rl = warp_m * 32 + mt * 16 + hf * 8 + g;
                size_t rowi = (size_t)bh2 * SEQ + n0 + rl;
                g_part[rowi * 16 + mq] =
                    make_float2(rmax[mt][hf], red[rl] + red[128 + rl]);
            }
    }
}

// ===========================================================================
// combine partials -> per-row (max, 1/sum)
__global__ __launch_bounds__(256) void combine_stats() {
    int idx = blockIdx.x * 256 + threadIdx.x;     // 0..65535
    int n = idx & (SEQ - 1);
    int nt = n >> 7;
    const float2* part = g_part + (size_t)idx * 16;
    float M = __int_as_float(0xff800000);
    for (int mq = 0; mq <= nt; mq++) M = fmaxf(M, part[mq].x);
    float S = 0.0f;
    for (int mq = 0; mq <= nt; mq++) S += part[mq].y * __expf(part[mq].x - M);
    g_rowstat[idx] = make_float2(M, 1.0f / S);
}

// ===========================================================================
// scores pass2: recompute QK^T, write normalized fp32 attnw + fp16 P.
__global__ __launch_bounds__(256, 2) void scores_p2(float* __restrict__ S) {
    const int bh2 = blockIdx.z, b = bh2 >> 4, h = bh2 & 15;
    int nq, mq; tri_index(blockIdx.x, nq, mq);
    const int n0 = nq * 128, m0 = mq * 128;
    GEMM_DECL();
    const float NEG_INF = __int_as_float(0xff800000);
    float* out = S + (size_t)bh2 * SEQ * SEQ;
    __half* ph = g_p_hi + (size_t)bh2 * SEQ * SEQ;
    const size_t qoff = (size_t)b * SEQ * E3 + (size_t)n0 * E3 + h * HD;
    const size_t koff = (size_t)b * SEQ * E3 + (size_t)m0 * E3 + EMB + h * HD;
    pipe_single(g_qkv_hi + qoff, E3, g_qkv_hi + koff, E3,
                HD / 64, sb, tid, warp_m, warp_n, lane, acc);
    __syncthreads();
    float2* stat = reinterpret_cast<float2*>(smc);   // [128] (max, invS)
    if (tid < 128) stat[tid] = g_rowstat[(size_t)bh2 * SEQ + n0 + tid];
    __syncthreads();
    const int g = lane >> 2, t = lane & 3;
#pragma unroll
    for (int mt = 0; mt < 2; mt++)
#pragma unroll
        for (int nt = 0; nt < 8; nt++) {
            int rl = warp_m * 32 + mt * 16 + g;
            int r = n0 + rl;
            int c = m0 + warp_n * 64 + nt * 8 + t * 2;
            float2 s0 = stat[rl], s1 = stat[rl + 8];
            float x0 = (c     <= r)     ? acc[mt][nt][0] * SCALE : NEG_INF;
            float x1 = (c + 1 <= r)     ? acc[mt][nt][1] * SCALE : NEG_INF;
            float x2 = (c     <= r + 8) ? acc[mt][nt][2] * SCALE : NEG_INF;
            float x3 = (c + 1 <= r + 8) ? acc[mt][nt][3] * SCALE : NEG_INF;
            float2 p0 = make_float2(__expf(x0 - s0.x) * s0.y,
                                    __expf(x1 - s0.x) * s0.y);
            float2 p1 = make_float2(__expf(x2 - s1.x) * s1.y,
                                    __expf(x3 - s1.x) * s1.y);
            stcs_f2(out + (size_t)r * SEQ + c, p0);
            stcs_f2(out + (size_t)(r + 8) * SEQ + c, p1);
            asm volatile("st.global.cs.u32 [%0], %1;"
                :: "l"(ph + (size_t)r * SEQ + c), "r"(round_pair_h(p0.x, p0.y)) : "memory");
            asm volatile("st.global.cs.u32 [%0], %1;"
                :: "l"(ph + (size_t)(r + 8) * SEQ + c), "r"(round_pair_h(p1.x, p1.y)) : "memory");
        }
}

// ===========================================================================
// zero-fill attnw upper-triangular tail, one CTA per row.
__global__ __launch_bounds__(128) void zerofill(float* __restrict__ P) {
    const size_t rowi = blockIdx.x;
    const int n = (int)(rowi & (SEQ - 1));
    const int b128 = ((n >> 7) + 1) << 7;
    if (b128 >= SEQ) return;
    float* p = P + rowi * SEQ + b128;
    const int cnt4 = (SEQ - b128) >> 2;
    float4 z = make_float4(0.f, 0.f, 0.f, 0.f);
    for (int i = threadIdx.x; i < cnt4; i += 128)
        stcs_f4(p + i * 4, z);
}

// ===========================================================================
__global__ __launch_bounds__(256, 2) void gemm_pv() {
    GEMM_DECL();
    const int bh2 = blockIdx.z, b = bh2 >> 4, h = bh2 & 15;
    const int n0 = (15 - blockIdx.y) * 128;    // big tiles first
    const size_t poff = (size_t)bh2 * SEQ * SEQ + (size_t)n0 * SEQ;
    const size_t voff = (size_t)bh2 * HD * SEQ;
    pipe_single(g_p_hi + poff, SEQ, g_vt_hi + voff, SEQ,
                (n0 + 128) / 64, sb, tid, warp_m, warp_n, lane, acc);
    const int g = lane >> 2, t = lane & 3;
#pragma unroll
    for (int mt = 0; mt < 2; mt++)
#pragma unroll
        for (int nt = 0; nt < 8; nt++) {
            int r = n0 + warp_m * 32 + mt * 16 + g;
            int c = warp_n * 64 + nt * 8 + t * 2;
            size_t o0 = (size_t)(b * SEQ + r) * EMB + h * HD + c;
            size_t o1 = o0 + (size_t)8 * EMB;
            *reinterpret_cast<uint32_t*>(g_attn_hi + o0) =
                round_pair_h(acc[mt][nt][0], acc[mt][nt][1]);
            *reinterpret_cast<uint32_t*>(g_attn_hi + o1) =
                round_pair_h(acc[mt][nt][2], acc[mt][nt][3]);
        }
}

// ===========================================================================
__global__ __launch_bounds__(256, 2) void gemm_proj(float* __restrict__ C,
                                                    const float* __restrict__ bias) {
    GEMM_DECL();
    const int m0 = blockIdx.y * 128, n0 = blockIdx.x * 128;
    pipe_single(g_attn_hi + (size_t)m0 * EMB, EMB,
                g_wpT_hi + (size_t)n0 * EMB, EMB,
                EMB / 64, sb, tid, warp_m, warp_n, lane, acc);
    const int g = lane >> 2, t = lane & 3;
#pragma unroll
    for (int mt = 0; mt < 2; mt++)
#pragma unroll
        for (int nt = 0; nt < 8; nt++) {
            int r = m0 + warp_m * 32 + mt * 16 + g;
            int c = n0 + warp_n * 64 + nt * 8 + t * 2;
            float2 bv = *reinterpret_cast<const float2*>(bias + c);
            *reinterpret_cast<float2*>(C + (size_t)r * EMB + c) =
                make_float2(acc[mt][nt][0] + bv.x, acc[mt][nt][1] + bv.y);
            *reinterpret_cast<float2*>(C + (size_t)(r + 8) * EMB + c) =
                make_float2(acc[mt][nt][2] + bv.x, acc[mt][nt][3] + bv.y);
        }
}

// ===========================================================================
__global__ __launch_bounds__(256) void round_hidden(const float* __restrict__ in) {
    size_t i = ((size_t)blockIdx.x * 256 + threadIdx.x) * 4;
    float4 v = *reinterpret_cast<const float4*>(in + i);
    *reinterpret_cast<uint2*>(g_hid_hi + i) =
        make_uint2(round_pair_h(v.x, v.y), round_pair_h(v.z, v.w));
}

__global__ void transpose_h(const float* __restrict__ in, int rows, int cols,
                            __half* __restrict__ oh) {
    __shared__ float t[32][33];
    int c0 = blockIdx.x * 32, r0 = blockIdx.y * 32;
    int tx = threadIdx.x, ty = threadIdx.y;
#pragma unroll
    for (int j = 0; j < 32; j += 8)
        t[ty + j][tx] = in[(size_t)(r0 + ty + j) * cols + c0 + tx];
    __syncthreads();
#pragma unroll
    for (int j = 0; j < 32; j += 8)
        oh[(size_t)(c0 + ty + j) * rows + r0 + tx] = __float2half_rn(t[tx][ty + j]);
}

__global__ void transpose_v() {
    __shared__ __half th[32][34];
    int bh2 = blockIdx.z, b = bh2 >> 4, h = bh2 & 15;
    const size_t base = (size_t)b * SEQ * E3 + 2 * EMB + h * HD;
    __half* oh = g_vt_hi + (size_t)bh2 * HD * SEQ;
    int c0 = blockIdx.x * 32, r0 = blockIdx.y * 32;
    int tx = threadIdx.x, ty = threadIdx.y;
#pragma unroll
    for (int j = 0; j < 32; j += 8)
        th[ty + j][tx] = g_qkv_hi[base + (size_t)(r0 + ty + j) * E3 + c0 + tx];
    __syncthreads();
#pragma unroll
    for (int j = 0; j < 32; j += 8)
        oh[(size_t)(c0 + ty + j) * SEQ + r0 + tx] = th[tx][ty + j];
}

// ===========================================================================
extern "C" void kernel_launch(void* const* d_in, const int* in_sizes, int n_in,
                              void* d_out, int out_size)
{
    (void)in_sizes; (void)n_in; (void)out_size;
    const float* hidden  = (const float*)d_in[0];
    const float* w_fused = (const float*)d_in[1];
    const float* w_proj  = (const float*)d_in[2];
    const float* b_proj  = (const float*)d_in[3];

    float* out   = (float*)d_out;
    float* attnw = out + (size_t)ROWS * EMB;

    cudaFuncSetAttribute(gemm_qkv,  cudaFuncAttributeMaxDynamicSharedMemorySize, SM_SNG);
    cudaFuncSetAttribute(scores_p1, cudaFuncAttributeMaxDynamicSharedMemorySize, SM_SNG);
    cudaFuncSetAttribute(scores_p2, cudaFuncAttributeMaxDynamicSharedMemorySize, SM_SNG);
    cudaFuncSetAttribute(gemm_pv,   cudaFuncAttributeMaxDynamicSharedMemorySize, SM_SNG);
    cudaFuncSetAttribute(gemm_proj, cudaFuncAttributeMaxDynamicSharedMemorySize, SM_SNG);

    __half *wfh, *wph;
    cudaGetSymbolAddress((void**)&wfh, g_wfT_hi);
    cudaGetSymbolAddress((void**)&wph, g_wpT_hi);

    // operand prep
    round_hidden<<<(ROWS * EMB) / 1024, 256>>>(hidden);
    transpose_h<<<dim3(E3 / 32, EMB / 32), dim3(32, 8)>>>(w_fused, EMB, E3, wfh);
    transpose_h<<<dim3(EMB / 32, EMB / 32), dim3(32, 8)>>>(w_proj, EMB, EMB, wph);

    // 1) qkv
    gemm_qkv<<<dim3(E3 / 128, ROWS / 128), 256, SM_SNG>>>();

    // V^T per head
    transpose_v<<<dim3(HD / 32, SEQ / 32, BSZ * NH), dim3(32, 8)>>>();

    // 2) scores pass1 (stats only) -> combine -> pass2 (normalized writes)
    scores_p1<<<dim3(136, 1, BSZ * NH), 256, SM_SNG>>>();
    combine_stats<<<(BSZ * NH * SEQ) / 256, 256>>>();
    scores_p2<<<dim3(136, 1, BSZ * NH), 256, SM_SNG>>>(attnw);
    zerofill<<<BSZ * NH * SEQ, 128>>>(attnw);

    // 3) attn_out = P @ V (big tiles first)
    gemm_pv<<<dim3(1, SEQ / 128, BSZ * NH), 256, SM_SNG>>>();

    // 4) out = attn_out @ w_proj + b_proj
    gemm_proj<<<dim3(EMB / 128, ROWS / 128), 256, SM_SNG>>>(out, b_proj);
}

// round 16
// speedup vs baseline: 1.0378x; 1.0378x over previous
#include <cuda_runtime.h>
#include <cuda_fp16.h>
#include <cstdint>
#include <math.h>

#define BSZ 2
#define SEQ 2048
#define EMB 2048
#define NH  16
#define HD  128
#define E3  (3*EMB)
#define ROWS (BSZ*SEQ)
#define SCALE 0.08838834764831845f

// ---------------- static device scratch (no allocations) ------------------
__device__ __half g_hid_hi[(size_t)ROWS * EMB];
__device__ __half g_qkv_hi[(size_t)ROWS * E3];
__device__ __half g_attn_hi[(size_t)ROWS * EMB];
__device__ __half g_wfT_hi[(size_t)E3 * EMB];
__device__ __half g_wpT_hi[(size_t)EMB * EMB];
__device__ __half g_vt_hi[(size_t)BSZ * NH * HD * SEQ];
__device__ __half g_p_hi[(size_t)BSZ * NH * SEQ * SEQ];

// ---------------- tile geometry (all GEMMs single-pass, KC=64) -------------
#define T64STR 72
#define T64B   (128 * T64STR * 2)      // 18432 B
#define SNG_STAGE (2 * T64B)           // A, B = 36864 B
#define SM_SNG (3 * SNG_STAGE)         // 110592 B -> 2 CTAs/SM (221 KB)

__device__ __forceinline__ uint32_t smem_u32(const void* p) {
    uint32_t a;
    asm("{ .reg .u64 t; cvta.to.shared.u64 t, %1; cvt.u32.u64 %0, t; }"
        : "=r"(a) : "l"(p));
    return a;
}
__device__ __forceinline__ void cpa16(uint32_t d, const void* s) {
    asm volatile("cp.async.cg.shared.global [%0], [%1], 16;" :: "r"(d), "l"(s) : "memory");
}
#define CP_COMMIT() asm volatile("cp.async.commit_group;" ::: "memory")
#define CP_WAIT1()  asm volatile("cp.async.wait_group 1;" ::: "memory")

#define LDMX4(r, a)                                                          \
    asm volatile("ldmatrix.sync.aligned.m8n8.x4.shared.b16 {%0,%1,%2,%3}, [%4];" \
                 : "=r"((r)[0]), "=r"((r)[1]), "=r"((r)[2]), "=r"((r)[3]) : "r"(a))

#define MMA16816(d, a, b0v, b1v)                                             \
    asm volatile("mma.sync.aligned.m16n8k16.row.col.f32.f16.f16.f32 "        \
                 "{%0,%1,%2,%3}, {%4,%5,%6,%7}, {%8,%9}, {%0,%1,%2,%3};"     \
                 : "+f"((d)[0]), "+f"((d)[1]), "+f"((d)[2]), "+f"((d)[3])    \
                 : "r"((a)[0]), "r"((a)[1]), "r"((a)[2]), "r"((a)[3]),       \
                   "r"(b0v), "r"(b1v))

__device__ __forceinline__ uint32_t round_pair_h(float x, float y) {
    __half2 H = __floats2half2_rn(x, y);
    return *reinterpret_cast<uint32_t*>(&H);
}
__device__ __forceinline__ void stcs_f2(float* p, float2 v) {
    asm volatile("st.global.cs.v2.f32 [%0], {%1,%2};" :: "l"(p), "f"(v.x), "f"(v.y) : "memory");
}
__device__ __forceinline__ void stcs_f4(float* p, float4 v) {
    asm volatile("st.global.cs.v4.f32 [%0], {%1,%2,%3,%4};"
                 :: "l"(p), "f"(v.x), "f"(v.y), "f"(v.z), "f"(v.w) : "memory");
}
__device__ __forceinline__ void stcs_u2(void* p, uint2 v) {
    asm volatile("st.global.cs.v2.u32 [%0], {%1,%2};" :: "l"(p), "r"(v.x), "r"(v.y) : "memory");
}
__device__ __forceinline__ float4 ldcs_f4(const float* p) {
    float4 v;
    asm volatile("ld.global.cs.v4.f32 {%0,%1,%2,%3}, [%4];"
                 : "=f"(v.x), "=f"(v.y), "=f"(v.z), "=f"(v.w) : "l"(p));
    return v;
}

// ======================= single-A GEMM core (KC=64, 3-stage) ===============
__device__ __forceinline__ void issue64(const __half* __restrict__ ah, int lda,
                                        const __half* __restrict__ bh, int ldb,
                                        uint32_t stage, int tid) {
#pragma unroll
    for (int i = 0; i < 4; i++) {
        int f = tid + i * 256;
        int r = f >> 3, kg = f & 7;
        uint32_t off = (uint32_t)(r * 144 + kg * 16);
        cpa16(stage + off, ah + (size_t)r * lda + kg * 8);
        cpa16(stage + T64B + off, bh + (size_t)r * ldb + kg * 8);
    }
}

__device__ __forceinline__ void mma64(uint32_t st, int warp_m, int warp_n,
                                      int lane, float acc[2][8][4]) {
    const int arow = (lane & 7) + ((lane >> 3) & 1) * 8;
    const int acol = (lane >> 4) * 8;
    const int brow = (lane & 7) + (lane >> 4) * 8;
    const int bcol = ((lane >> 3) & 1) * 8;
#pragma unroll
    for (int k16 = 0; k16 < 4; k16++) {
        const int k0 = k16 * 16;
        uint32_t ah[2][4];
#pragma unroll
        for (int mt = 0; mt < 2; mt++) {
            uint32_t a = st +
                (uint32_t)((warp_m * 32 + mt * 16 + arow) * T64STR + k0 + acol) * 2;
            LDMX4(ah[mt], a);
        }
#pragma unroll
        for (int np = 0; np < 4; np++) {
            uint32_t b = st + T64B +
                (uint32_t)((warp_n * 64 + np * 16 + brow) * T64STR + k0 + bcol) * 2;
            uint32_t bh[4];
            LDMX4(bh, b);
#pragma unroll
            for (int mt = 0; mt < 2; mt++) {
                MMA16816(acc[mt][2 * np],     ah[mt], bh[0], bh[1]);
                MMA16816(acc[mt][2 * np + 1], ah[mt], bh[2], bh[3]);
            }
        }
    }
}

__device__ __forceinline__ void pipe_single(
    const __half* ah, int lda, const __half* bh, int ldb, int nch, uint32_t sb,
    int tid, int warp_m, int warp_n, int lane, float acc[2][8][4])
{
#pragma unroll
    for (int s = 0; s < 2; s++) {
        if (s < nch) issue64(ah + s * 64, lda, bh + s * 64, ldb,
                             sb + s * SNG_STAGE, tid);
        CP_COMMIT();
    }
    for (int c = 0; c < nch; c++) {
        CP_WAIT1();
        __syncthreads();
        mma64(sb + (c % 3) * SNG_STAGE, warp_m, warp_n, lane, acc);
        if (c + 2 < nch)
            issue64(ah + (c + 2) * 64, lda, bh + (c + 2) * 64, ldb,
                    sb + ((c + 2) % 3) * SNG_STAGE, tid);
        CP_COMMIT();
    }
}

#define GEMM_DECL()                                                          \
    extern __shared__ char smc[];                                            \
    uint32_t sb = smem_u32(smc);                                             \
    const int tid = threadIdx.x;                                             \
    const int wid = tid >> 5, lane = tid & 31;                               \
    const int warp_m = wid & 3, warp_n = wid >> 2;                           \
    float acc[2][8][4];                                                      \
    _Pragma("unroll") for (int i = 0; i < 2; i++)                            \
    _Pragma("unroll") for (int j = 0; j < 8; j++)                            \
    _Pragma("unroll") for (int q = 0; q < 4; q++) acc[i][j][q] = 0.0f;

// ===========================================================================
__global__ __launch_bounds__(256, 2) void gemm_qkv() {
    GEMM_DECL();
    const int m0 = blockIdx.y * 128, n0 = blockIdx.x * 128;
    pipe_single(g_hid_hi + (size_t)m0 * EMB, EMB,
                g_wfT_hi + (size_t)n0 * EMB, EMB,
                EMB / 64, sb, tid, warp_m, warp_n, lane, acc);
    const int g = lane >> 2, t = lane & 3;
#pragma unroll
    for (int mt = 0; mt < 2; mt++)
#pragma unroll
        for (int nt = 0; nt < 8; nt++) {
            int r = m0 + warp_m * 32 + mt * 16 + g;
            int c = n0 + warp_n * 64 + nt * 8 + t * 2;
            size_t o0 = (size_t)r * E3 + c, o1 = (size_t)(r + 8) * E3 + c;
            *reinterpret_cast<uint32_t*>(g_qkv_hi + o0) =
                round_pair_h(acc[mt][nt][0], acc[mt][nt][1]);
            *reinterpret_cast<uint32_t*>(g_qkv_hi + o1) =
                round_pair_h(acc[mt][nt][2], acc[mt][nt][3]);
        }
}

// ===========================================================================
// scores: compact triangular grid (x: 136 tri tiles, z: 32 heads).
__global__ __launch_bounds__(256, 2) void gemm_scores(float* __restrict__ S) {
    const int bh2 = blockIdx.z, b = bh2 >> 4, h = bh2 & 15;
    const int q = blockIdx.x;           // 0..135 lower-tri tile index
    int nq = (int)((sqrtf(8.0f * (float)q + 1.0f) - 1.0f) * 0.5f);
    while ((nq + 1) * (nq + 2) / 2 <= q) nq++;
    while (nq * (nq + 1) / 2 > q) nq--;
    const int mq = q - nq * (nq + 1) / 2;
    const int n0 = nq * 128, m0 = mq * 128;
    GEMM_DECL();
    float* out = S + (size_t)bh2 * SEQ * SEQ;
    const float NEG_INF = __int_as_float(0xff800000);
    const size_t qoff = (size_t)b * SEQ * E3 + (size_t)n0 * E3 + h * HD;
    const size_t koff = (size_t)b * SEQ * E3 + (size_t)m0 * E3 + EMB + h * HD;
    pipe_single(g_qkv_hi + qoff, E3,
                g_qkv_hi + koff, E3,
                HD / 64, sb, tid, warp_m, warp_n, lane, acc);
    const int g = lane >> 2, t = lane & 3;
#pragma unroll
    for (int mt = 0; mt < 2; mt++)
#pragma unroll
        for (int nt = 0; nt < 8; nt++) {
            int r = n0 + warp_m * 32 + mt * 16 + g;
            int c = m0 + warp_n * 64 + nt * 8 + t * 2;
            float2 v0, v1;
            v0.x = (c     <= r) ? acc[mt][nt][0] * SCALE : NEG_INF;
            v0.y = (c + 1 <= r) ? acc[mt][nt][1] * SCALE : NEG_INF;
            v1.x = (c     <= r + 8) ? acc[mt][nt][2] * SCALE : NEG_INF;
            v1.y = (c + 1 <= r + 8) ? acc[mt][nt][3] * SCALE : NEG_INF;
            stcs_f2(out + (size_t)r * SEQ + c, v0);
            stcs_f2(out + (size_t)(r + 8) * SEQ + c, v1);
        }
}

// ===========================================================================
// pv: big tiles first (reverse y) to pack the causal imbalance.
__global__ __launch_bounds__(256, 2) void gemm_pv() {
    GEMM_DECL();
    const int bh2 = blockIdx.z, b = bh2 >> 4, h = bh2 & 15;
    const int n0 = (15 - blockIdx.y) * 128;
    const size_t poff = (size_t)bh2 * SEQ * SEQ + (size_t)n0 * SEQ;
    const size_t voff = (size_t)bh2 * HD * SEQ;
    pipe_single(g_p_hi + poff, SEQ, g_vt_hi + voff, SEQ,
                (n0 + 128) / 64, sb, tid, warp_m, warp_n, lane, acc);
    const int g = lane >> 2, t = lane & 3;
#pragma unroll
    for (int mt = 0; mt < 2; mt++)
#pragma unroll
        for (int nt = 0; nt < 8; nt++) {
            int r = n0 + warp_m * 32 + mt * 16 + g;
            int c = warp_n * 64 + nt * 8 + t * 2;
            size_t o0 = (size_t)(b * SEQ + r) * EMB + h * HD + c;
            size_t o1 = o0 + (size_t)8 * EMB;
            *reinterpret_cast<uint32_t*>(g_attn_hi + o0) =
                round_pair_h(acc[mt][nt][0], acc[mt][nt][1]);
            *reinterpret_cast<uint32_t*>(g_attn_hi + o1) =
                round_pair_h(acc[mt][nt][2], acc[mt][nt][3]);
        }
}

// ===========================================================================
__global__ __launch_bounds__(256, 2) void gemm_proj(float* __restrict__ C,
                                                    const float* __restrict__ bias) {
    GEMM_DECL();
    const int m0 = blockIdx.y * 128, n0 = blockIdx.x * 128;
    pipe_single(g_attn_hi + (size_t)m0 * EMB, EMB,
                g_wpT_hi + (size_t)n0 * EMB, EMB,
                EMB / 64, sb, tid, warp_m, warp_n, lane, acc);
    const int g = lane >> 2, t = lane & 3;
#pragma unroll
    for (int mt = 0; mt < 2; mt++)
#pragma unroll
        for (int nt = 0; nt < 8; nt++) {
            int r = m0 + warp_m * 32 + mt * 16 + g;
            int c = n0 + warp_n * 64 + nt * 8 + t * 2;
            float2 bv = *reinterpret_cast<const float2*>(bias + c);
            *reinterpret_cast<float2*>(C + (size_t)r * EMB + c) =
                make_float2(acc[mt][nt][0] + bv.x, acc[mt][nt][1] + bv.y);
            *reinterpret_cast<float2*>(C + (size_t)(r + 8) * EMB + c) =
                make_float2(acc[mt][nt][2] + bv.x, acc[mt][nt][3] + bv.y);
        }
}

// ===========================================================================
// merged prep: [0,8192) round_hidden | [8192,20480) wf transpose |
//              [20480,24576) wp transpose. 256 threads each.
#define PREP_R 8192
#define PREP_WF (PREP_R + 12288)
#define PREP_TOTAL (PREP_WF + 4096)

__device__ __forceinline__ void transpose_body(const float* __restrict__ in,
                                               int rows, int cols,
                                               __half* __restrict__ oh,
                                               int c0, int r0, int tid) {
    __shared__ float t[32][33];
    int tx = tid & 31, ty = tid >> 5;
#pragma unroll
    for (int j = 0; j < 32; j += 8)
        t[ty + j][tx] = in[(size_t)(r0 + ty + j) * cols + c0 + tx];
    __syncthreads();
#pragma unroll
    for (int j = 0; j < 32; j += 8)
        oh[(size_t)(c0 + ty + j) * rows + r0 + tx] = __float2half_rn(t[tx][ty + j]);
}

__global__ __launch_bounds__(256) void prep_all(const float* __restrict__ hidden,
                                                const float* __restrict__ wf,
                                                const float* __restrict__ wp) {
    const int bid = blockIdx.x;
    const int tid = threadIdx.x;
    if (bid < PREP_R) {
        size_t i = ((size_t)bid * 256 + tid) * 4;
        float4 v = *reinterpret_cast<const float4*>(hidden + i);
        *reinterpret_cast<uint2*>(g_hid_hi + i) =
            make_uint2(round_pair_h(v.x, v.y), round_pair_h(v.z, v.w));
    } else if (bid < PREP_WF) {
        int b = bid - PREP_R;                     // wf: rows=EMB, cols=E3
        int c0 = (b % (E3 / 32)) * 32, r0 = (b / (E3 / 32)) * 32;
        transpose_body(wf, EMB, E3, g_wfT_hi, c0, r0, tid);
    } else {
        int b = bid - PREP_WF;                    // wp: rows=EMB, cols=EMB
        int c0 = (b % (EMB / 32)) * 32, r0 = (b / (EMB / 32)) * 32;
        transpose_body(wp, EMB, EMB, g_wpT_hi, c0, r0, tid);
    }
}

__global__ void transpose_v() {
    __shared__ __half th[32][34];
    int bh2 = blockIdx.z, b = bh2 >> 4, h = bh2 & 15;
    const size_t base = (size_t)b * SEQ * E3 + 2 * EMB + h * HD;
    __half* oh = g_vt_hi + (size_t)bh2 * HD * SEQ;
    int c0 = blockIdx.x * 32, r0 = blockIdx.y * 32;
    int tx = threadIdx.x, ty = threadIdx.y;
#pragma unroll
    for (int j = 0; j < 32; j += 8)
        th[ty + j][tx] = g_qkv_hi[base + (size_t)(r0 + ty + j) * E3 + c0 + tx];
    __syncthreads();
#pragma unroll
    for (int j = 0; j < 32; j += 8)
        oh[(size_t)(c0 + ty + j) * SEQ + r0 + tx] = th[tx][ty + j];
}

// ===========================================================================
// Softmax: shfl reductions (2 barriers), streaming hints.
__global__ __launch_bounds__(256) void softmax_kernel(float* __restrict__ P) {
    const size_t rowi = blockIdx.x;
    const int n = (int)(rowi & (SEQ - 1));
    const int b128 = ((n >> 7) + 1) << 7;
    float* p = P + rowi * SEQ;
    __half* ph = g_p_hi + rowi * SEQ;
    const int tid = threadIdx.x;
    const int lane = tid & 31, wrp = tid >> 5;
    const int c0 = tid * 4, c1 = 1024 + tid * 4;
    const float NEG_INF = __int_as_float(0xff800000);

    float4 v0 = make_float4(NEG_INF, NEG_INF, NEG_INF, NEG_INF);
    float4 v1 = v0;
    if (c0 < b128) v0 = ldcs_f4(p + c0);
    if (c1 < b128) v1 = ldcs_f4(p + c1);

    float m = fmaxf(fmaxf(fmaxf(v0.x, v0.y), fmaxf(v0.z, v0.w)),
                    fmaxf(fmaxf(v1.x, v1.y), fmaxf(v1.z, v1.w)));
#pragma unroll
    for (int o = 16; o; o >>= 1)
        m = fmaxf(m, __shfl_xor_sync(0xFFFFFFFFu, m, o));
    __shared__ float wmax[8], wsum[8];
    if (lane == 0) wmax[wrp] = m;
    __syncthreads();
    float rmax = fmaxf(fmaxf(fmaxf(wmax[0], wmax[1]), fmaxf(wmax[2], wmax[3])),
                       fmaxf(fmaxf(wmax[4], wmax[5]), fmaxf(wmax[6], wmax[7])));

    v0.x = __expf(v0.x - rmax); v0.y = __expf(v0.y - rmax);
    v0.z = __expf(v0.z - rmax); v0.w = __expf(v0.w - rmax);
    v1.x = __expf(v1.x - rmax); v1.y = __expf(v1.y - rmax);
    v1.z = __expf(v1.z - rmax); v1.w = __expf(v1.w - rmax);

    float s = v0.x + v0.y + v0.z + v0.w + v1.x + v1.y + v1.z + v1.w;
#pragma unroll
    for (int o = 16; o; o >>= 1)
        s += __shfl_xor_sync(0xFFFFFFFFu, s, o);
    if (lane == 0) wsum[wrp] = s;
    __syncthreads();
    float inv = 1.0f / (wsum[0] + wsum[1] + wsum[2] + wsum[3] +
                        wsum[4] + wsum[5] + wsum[6] + wsum[7]);

    v0.x *= inv; v0.y *= inv; v0.z *= inv; v0.w *= inv;
    v1.x *= inv; v1.y *= inv; v1.z *= inv; v1.w *= inv;
    stcs_f4(p + c0, v0);
    stcs_f4(p + c1, v1);

    if (c0 < b128)
        stcs_u2(ph + c0, make_uint2(round_pair_h(v0.x, v0.y), round_pair_h(v0.z, v0.w)));
    if (c1 < b128)
        stcs_u2(ph + c1, make_uint2(round_pair_h(v1.x, v1.y), round_pair_h(v1.z, v1.w)));
}

// ===========================================================================
extern "C" void kernel_launch(void* const* d_in, const int* in_sizes, int n_in,
                              void* d_out, int out_size)
{
    (void)in_sizes; (void)n_in; (void)out_size;
    const float* hidden  = (const float*)d_in[0];
    const float* w_fused = (const float*)d_in[1];
    const float* w_proj  = (const float*)d_in[2];
    const float* b_proj  = (const float*)d_in[3];

    float* out   = (float*)d_out;
    float* attnw = out + (size_t)ROWS * EMB;

    cudaFuncSetAttribute(gemm_qkv,    cudaFuncAttributeMaxDynamicSharedMemorySize, SM_SNG);
    cudaFuncSetAttribute(gemm_scores, cudaFuncAttributeMaxDynamicSharedMemorySize, SM_SNG);
    cudaFuncSetAttribute(gemm_pv,     cudaFuncAttributeMaxDynamicSharedMemorySize, SM_SNG);
    cudaFuncSetAttribute(gemm_proj,   cudaFuncAttributeMaxDynamicSharedMemorySize, SM_SNG);

    // merged operand prep (round + both weight transposes)
    prep_all<<<PREP_TOTAL, 256>>>(hidden, w_fused, w_proj);

    // 1) qkv (single-pass fp16)
    gemm_qkv<<<dim3(E3 / 128, ROWS / 128), 256, SM_SNG>>>();

    // V^T per head
    transpose_v<<<dim3(HD / 32, SEQ / 32, BSZ * NH), dim3(32, 8)>>>();

    // 2) scores (compact triangular grid)
    gemm_scores<<<dim3(136, 1, BSZ * NH), 256, SM_SNG>>>(attnw);

    // 3) softmax (shfl reductions, streaming hints)
    softmax_kernel<<<BSZ * NH * SEQ, 256>>>(attnw);

    // 4) attn_out = P @ V (big tiles first)
    gemm_pv<<<dim3(1, SEQ / 128, BSZ * NH), 256, SM_SNG>>>();

    // 5) out = attn_out @ w_proj + b_proj
    gemm_proj<<<dim3(EMB / 128, ROWS / 128), 256, SM_SNG>>>(out, b_proj);
}